// round 13
// baseline (speedup 1.0000x reference)
#include <cuda_runtime.h>
#include <cuda_bf16.h>
#include <cuda_fp16.h>
#include <cstdint>
#include <math.h>

#define BB 2
#define SS 2048
#define DD 1024
#define HH 16
#define DHH 64
#define MM (BB * SS)

// ---------------- scratch (device globals: allocation-free rule) -----------
__device__ __half g_xh[(size_t)MM * DD], g_xl[(size_t)MM * DD];
__device__ __half g_Wth[(size_t)4 * DD * DD];                      // hi only
__device__ __half g_Qh[(size_t)MM * DD], g_Ql[(size_t)MM * DD];
__device__ __half g_Kh[(size_t)MM * DD];
__device__ __half g_Vth[(size_t)MM * DD], g_Vtl[(size_t)MM * DD];  // [B][D][S]
__device__ __half g_AOh[(size_t)MM * DD], g_AOl[(size_t)MM * DD];

// ---------------- helpers --------------------------------------------------
__device__ __forceinline__ uint32_t smem_to_u32(const void* p) {
    uint32_t a;
    asm("{ .reg .u64 t; cvta.to.shared.u64 t, %1; cvt.u32.u64 %0, t; }"
        : "=r"(a) : "l"(p));
    return a;
}
__device__ __forceinline__ void ldsm4(uint32_t addr, uint32_t& r0, uint32_t& r1,
                                      uint32_t& r2, uint32_t& r3) {
    asm volatile("ldmatrix.sync.aligned.m8n8.x4.shared.b16 {%0,%1,%2,%3}, [%4];"
                 : "=r"(r0), "=r"(r1), "=r"(r2), "=r"(r3) : "r"(addr));
}
__device__ __forceinline__ void mma_f16(float* d, const uint32_t* a, const uint32_t* b) {
    asm volatile(
        "mma.sync.aligned.m16n8k16.row.col.f32.f16.f16.f32 "
        "{%0,%1,%2,%3}, {%4,%5,%6,%7}, {%8,%9}, {%0,%1,%2,%3};"
        : "+f"(d[0]), "+f"(d[1]), "+f"(d[2]), "+f"(d[3])
        : "r"(a[0]), "r"(a[1]), "r"(a[2]), "r"(a[3]), "r"(b[0]), "r"(b[1]));
}
__device__ __forceinline__ void hf_split(float x, __half& h, __half& l) {
    h = __float2half_rn(x);
    l = __float2half_rn(x - __half2float(h));
}
__device__ __forceinline__ uint32_t pack_h2(__half a, __half b) {
    __half2 t(a, b);
    return *reinterpret_cast<uint32_t*>(&t);
}
__device__ __forceinline__ uint32_t pack_f2h2(float a, float b) {
    __half2 t = __floats2half2_rn(a, b);
    return *reinterpret_cast<uint32_t*>(&t);
}
#define CPA16(dst, src) \
    asm volatile("cp.async.cg.shared.global [%0], [%1], 16;" :: "r"(dst), "l"(src))
#define CPCOMMIT() asm volatile("cp.async.commit_group;" ::: "memory")
#define CPWAIT(n)  asm volatile("cp.async.wait_group %0;" :: "n"(n) : "memory")

// swizzle for [rows][32 x 16-bit] tiles (64B rows, 4x16B chunks)
__device__ __forceinline__ uint32_t swz(int row, int chunk) {
    return (uint32_t)(row * 64 + ((chunk ^ ((row >> 1) & 3)) << 4));
}
// swizzle for [rows][64 x 16-bit] tiles (128B rows, 8x16B chunks)
__device__ __forceinline__ uint32_t sw8(int row, int c8) {
    return (uint32_t)(row * 128 + ((c8 ^ (row & 7)) << 4));
}

// ---------------- conversion kernels ---------------------------------------
__global__ __launch_bounds__(256) void conv_split(
    const float* __restrict__ X, __half* __restrict__ H,
    __half* __restrict__ L, int n4)
{
    int i = blockIdx.x * 256 + threadIdx.x;
    if (i >= n4) return;
    float4 v = reinterpret_cast<const float4*>(X)[i];
    __half h0, l0, h1, l1, h2, l2, h3, l3;
    hf_split(v.x, h0, l0); hf_split(v.y, h1, l1);
    hf_split(v.z, h2, l2); hf_split(v.w, h3, l3);
    reinterpret_cast<uint2*>(H)[i] = make_uint2(pack_h2(h0, h1), pack_h2(h2, h3));
    reinterpret_cast<uint2*>(L)[i] = make_uint2(pack_h2(l0, l1), pack_h2(l2, l3));
}

__global__ __launch_bounds__(256) void conv_wt(
    const float* __restrict__ W0, const float* __restrict__ W1,
    const float* __restrict__ W2, const float* __restrict__ W3,
    __half* __restrict__ H)
{
    __shared__ float t[32][33];
    const int mat = blockIdx.z;
    const float* W = (mat == 0) ? W0 : (mat == 1) ? W1 : (mat == 2) ? W2 : W3;
    const int r0 = blockIdx.y * 32, c0 = blockIdx.x * 32;
    const int tx = threadIdx.x & 31, ty = threadIdx.x >> 5;
#pragma unroll
    for (int j = 0; j < 4; j++)
        t[ty + j * 8][tx] = W[(size_t)(r0 + ty + j * 8) * DD + c0 + tx];
    __syncthreads();
#pragma unroll
    for (int j = 0; j < 4; j++) {
        size_t dst = (size_t)mat * DD * DD + (size_t)(c0 + ty + j * 8) * DD + r0 + tx;
        H[dst] = __float2half_rn(t[tx][ty + j * 8]);
    }
}

// ===========================================================================
// fp16x2 GEMM: C = (A_h + A_l) @ W_h + bias. Pre-converted inputs,
// cp.async 3-stage ring, single barrier/chunk, 2 CTAs/SM.
// CTA tile 128x128, BK=32, 8 warps (4Mx2N).
// Stage: A_hi 8K | A_lo 8K | B_hi 8K = 24KB.
// Outputs: m=0 -> Q (fp16 hi/lo), m=1 -> K (fp16 hi), m=2 -> Vt (fp16 hi/lo),
//          nmats==1 -> fp32 Cf.
// ===========================================================================
#define STG2 24576
#define GEMM_SMEM (3 * STG2)
#define NCHUNK 32

__global__ __launch_bounds__(256, 2) void gemm_f16x2(
    const __half* __restrict__ Ah, const __half* __restrict__ Al,
    const __half* __restrict__ Bth,
    const float* __restrict__ bias0, const float* __restrict__ bias1,
    const float* __restrict__ bias2,
    __half* __restrict__ Qh, __half* __restrict__ Ql,
    __half* __restrict__ Kh,
    __half* __restrict__ Vth, __half* __restrict__ Vtl,
    float* __restrict__ Cf, int nmats)
{
    extern __shared__ char smem[];
    const uint32_t sbase = smem_to_u32(smem);
    const int tid = threadIdx.x;
    const int wid = tid >> 5;
    const int lane = tid & 31;

    const int m = (nmats == 3) ? (int)(blockIdx.x >> 3) : 0;
    const __half* Bh_g = Bth + (size_t)m * DD * DD;
    const float* bias = (m == 0) ? bias0 : (m == 1) ? bias1 : bias2;
    const int bCol = (blockIdx.x & 7) * 128;
    const int bRow = blockIdx.y * 128;

    const int warpM = (wid >> 1) * 32;
    const int warpN = (wid & 1) * 64;
    const int sub = lane >> 3;
    const int li = lane & 7;

    int rA[2]; uint32_t baseA[2]; int swA[2];
#pragma unroll
    for (int fm = 0; fm < 2; fm++) {
        rA[fm] = warpM + fm * 16 + (sub & 1) * 8 + li;
        baseA[fm] = (uint32_t)(rA[fm] * 64);
        swA[fm] = (rA[fm] >> 1) & 3;
    }
    const int chA_off = sub >> 1;
    int rB[4]; uint32_t baseB[4]; int swB[4];
#pragma unroll
    for (int nb = 0; nb < 4; nb++) {
        rB[nb] = warpN + nb * 16 + ((sub >> 1) & 1) * 8 + li;
        baseB[nb] = (uint32_t)(rB[nb] * 64);
        swB[nb] = (rB[nb] >> 1) & 3;
    }
    const int chB_off = sub & 1;

    float acc[2][8][4];
#pragma unroll
    for (int fm = 0; fm < 2; fm++)
#pragma unroll
        for (int fn = 0; fn < 8; fn++)
#pragma unroll
            for (int r = 0; r < 4; r++) acc[fm][fn][r] = 0.0f;

#define LOAD_STAGE(s, c) do { \
        uint32_t st_ = sbase + (uint32_t)(s) * STG2; \
        _Pragma("unroll") \
        for (int p = 0; p < 2; p++) { \
            int id = tid + p * 256; \
            int row = id >> 2, c4 = id & 3; \
            size_t ga = (size_t)(bRow + row) * DD + (c) * 32 + c4 * 8; \
            uint32_t da = st_ + swz(row, c4); \
            CPA16(da, Ah + ga); \
            CPA16(da + 8192, Al + ga); \
            size_t gb = (size_t)(bCol + row) * DD + (c) * 32 + c4 * 8; \
            CPA16(st_ + 16384 + swz(row, c4), Bh_g + gb); \
        } \
    } while (0)

    LOAD_STAGE(0, 0); CPCOMMIT();
    LOAD_STAGE(1, 1); CPCOMMIT();

    for (int c = 0; c < NCHUNK; c++) {
        if (c < NCHUNK - 1) { CPWAIT(1); } else { CPWAIT(0); }
        __syncthreads();
        // Barrier above proves all warps done reading stage (c+2)%3.
        if (c + 2 < NCHUNK) { LOAD_STAGE((c + 2) % 3, c + 2); CPCOMMIT(); }

        const uint32_t st = sbase + (uint32_t)(c % 3) * STG2;
#pragma unroll
        for (int ks = 0; ks < 2; ks++) {
            uint32_t ah[2][4], al[2][4];
#pragma unroll
            for (int fm = 0; fm < 2; fm++) {
                uint32_t chunk = (uint32_t)((2 * ks + chA_off) ^ swA[fm]) << 4;
                ldsm4(st + baseA[fm] + chunk, ah[fm][0], ah[fm][1], ah[fm][2], ah[fm][3]);
                ldsm4(st + 8192 + baseA[fm] + chunk, al[fm][0], al[fm][1], al[fm][2], al[fm][3]);
            }
#pragma unroll
            for (int nb = 0; nb < 4; nb++) {
                uint32_t bh[4];
                uint32_t chunk = (uint32_t)((2 * ks + chB_off) ^ swB[nb]) << 4;
                ldsm4(st + 16384 + baseB[nb] + chunk, bh[0], bh[1], bh[2], bh[3]);
#pragma unroll
                for (int fm = 0; fm < 2; fm++)
#pragma unroll
                    for (int hf = 0; hf < 2; hf++) {
                        float* d = acc[fm][nb * 2 + hf];
                        mma_f16(d, ah[fm], &bh[hf * 2]);
                        mma_f16(d, al[fm], &bh[hf * 2]);
                    }
            }
        }
    }
#undef LOAD_STAGE

    // epilogue
#pragma unroll
    for (int fm = 0; fm < 2; fm++) {
        int row0 = bRow + warpM + fm * 16 + (lane >> 2);
#pragma unroll
        for (int fn = 0; fn < 8; fn++) {
            int col = bCol + warpN + fn * 8 + 2 * (lane & 3);
            float bx = bias[col], by = bias[col + 1];
            float v[4] = {acc[fm][fn][0] + bx, acc[fm][fn][1] + by,
                          acc[fm][fn][2] + bx, acc[fm][fn][3] + by};
            if (nmats == 1) {
                *reinterpret_cast<float2*>(&Cf[(size_t)row0 * DD + col]) =
                    make_float2(v[0], v[1]);
                *reinterpret_cast<float2*>(&Cf[(size_t)(row0 + 8) * DD + col]) =
                    make_float2(v[2], v[3]);
            } else if (m == 0) {
                __half h[4], l[4];
#pragma unroll
                for (int j = 0; j < 4; j++) hf_split(v[j], h[j], l[j]);
                *reinterpret_cast<uint32_t*>(&Qh[(size_t)row0 * DD + col]) = pack_h2(h[0], h[1]);
                *reinterpret_cast<uint32_t*>(&Ql[(size_t)row0 * DD + col]) = pack_h2(l[0], l[1]);
                *reinterpret_cast<uint32_t*>(&Qh[(size_t)(row0 + 8) * DD + col]) = pack_h2(h[2], h[3]);
                *reinterpret_cast<uint32_t*>(&Ql[(size_t)(row0 + 8) * DD + col]) = pack_h2(l[2], l[3]);
            } else if (m == 1) {
                *reinterpret_cast<uint32_t*>(&Kh[(size_t)row0 * DD + col]) = pack_f2h2(v[0], v[1]);
                *reinterpret_cast<uint32_t*>(&Kh[(size_t)(row0 + 8) * DD + col]) = pack_f2h2(v[2], v[3]);
            } else {
                // transposed: Vt[b][d][s], fp16 hi/lo
#pragma unroll
                for (int j = 0; j < 4; j++) {
                    int r = row0 + (j >> 1) * 8;
                    int cc = col + (j & 1);
                    size_t idx = ((size_t)(r >> 11) * DD + cc) * SS + (r & (SS - 1));
                    __half h, l; hf_split(v[j], h, l);
                    Vth[idx] = h; Vtl[idx] = l;
                }
            }
        }
    }
}

// ===========================================================================
// Tensor-core flash attention, fp16 2-term. CTA = 128 q rows of one (b,h).
// S = (q_h + q_l) . k_h;  O += p_h . (v_h + v_l).
// Stage: Kh 8KB | Vh 8KB | Vl 8KB = 24KB; 3 stages + 32KB Q = 104KB smem.
// ===========================================================================
#define AT_STG 24576
#define AT_Q   (3 * AT_STG)
#define ATTN_SMEM (3 * AT_STG + 32768)
#define NKT 32

__global__ __launch_bounds__(256, 2) void attn_tc(
    const __half* __restrict__ Qh_g, const __half* __restrict__ Ql_g,
    const __half* __restrict__ Kh_g,
    const __half* __restrict__ Vth_g, const __half* __restrict__ Vtl_g,
    __half* __restrict__ AOh, __half* __restrict__ AOl)
{
    extern __shared__ char smem[];
    const uint32_t sb = smem_to_u32(smem);
    const int tid = threadIdx.x;
    const int wid = tid >> 5;
    const int lane = tid & 31;
    const int sub = lane >> 3;
    const int li = lane & 7;
    const int bh = blockIdx.y;
    const int b = bh >> 4, h = bh & 15;
    const int q0 = blockIdx.x * 128;

    // Q tile (hi at +0, lo at +16384)
    const uint32_t qreg = sb + AT_Q;
#pragma unroll
    for (int p = 0; p < 4; p++) {
        int id = tid + p * 256;            // 0..1023
        int row = id >> 3, c8 = id & 7;
        size_t src = (size_t)(b * SS + q0 + row) * DD + h * DHH + c8 * 8;
        CPA16(qreg + sw8(row, c8), Qh_g + src);
        CPA16(qreg + 16384 + sw8(row, c8), Ql_g + src);
    }
    CPCOMMIT();

#define LOAD_KV(s, kt) do { \
        uint32_t st_ = sb + (uint32_t)(s) * AT_STG; \
        _Pragma("unroll") \
        for (int p = 0; p < 2; p++) { \
            int id = tid + p * 256; \
            int row = id >> 3, c8 = id & 7; \
            size_t ks_ = (size_t)(b * SS + (kt) * 64 + row) * DD + h * DHH + c8 * 8; \
            CPA16(st_ + sw8(row, c8), Kh_g + ks_); \
            size_t vs_ = (size_t)(b * DD + h * DHH + row) * SS + (kt) * 64 + c8 * 8; \
            CPA16(st_ + 8192 + sw8(row, c8), Vth_g + vs_); \
            CPA16(st_ + 16384 + sw8(row, c8), Vtl_g + vs_); \
        } \
    } while (0)

    LOAD_KV(0, 0); CPCOMMIT();
    LOAD_KV(1, 1); CPCOMMIT();

    CPWAIT(2);          // Q arrived
    __syncthreads();

    // Q fragments for all 4 k-chunks (d=64), hi+lo -> registers
    uint32_t qh[4][4], ql[4][4];
    {
        int r = wid * 16 + (sub & 1) * 8 + li;
#pragma unroll
        for (int kc = 0; kc < 4; kc++) {
            int c16 = 2 * kc + (sub >> 1);
            uint32_t a = qreg + (uint32_t)(r * 128 + ((c16 ^ (r & 7)) << 4));
            ldsm4(a, qh[kc][0], qh[kc][1], qh[kc][2], qh[kc][3]);
            ldsm4(a + 16384, ql[kc][0], ql[kc][1], ql[kc][2], ql[kc][3]);
        }
    }

    float oacc[8][4];
#pragma unroll
    for (int i = 0; i < 8; i++)
#pragma unroll
        for (int j = 0; j < 4; j++) oacc[i][j] = 0.0f;
    float sum0 = 0.0f, sum1 = 0.0f;

    const int rKV = ((sub >> 1) & 1) * 8 + li;
    const int chKV = sub & 1;

    for (int kt = 0; kt < NKT; kt++) {
        if (kt < NKT - 1) { CPWAIT(1); } else { CPWAIT(0); }
        __syncthreads();
        if (kt + 2 < NKT) { LOAD_KV((kt + 2) % 3, kt + 2); CPCOMMIT(); }

        const uint32_t st = sb + (uint32_t)(kt % 3) * AT_STG;

        float sacc[8][4];
#pragma unroll
        for (int i = 0; i < 8; i++)
#pragma unroll
            for (int j = 0; j < 4; j++) sacc[i][j] = 0.0f;

#pragma unroll
        for (int kg = 0; kg < 4; kg++) {
            int row = kg * 16 + rKV;
#pragma unroll
            for (int kc = 0; kc < 4; kc++) {
                int c16 = 2 * kc + chKV;
                uint32_t a = st + (uint32_t)(row * 128 + ((c16 ^ (row & 7)) << 4));
                uint32_t kh[4];
                ldsm4(a, kh[0], kh[1], kh[2], kh[3]);
#pragma unroll
                for (int hf = 0; hf < 2; hf++) {
                    float* d = sacc[kg * 2 + hf];
                    mma_f16(d, qh[kc], &kh[hf * 2]);
                    mma_f16(d, ql[kc], &kh[hf * 2]);
                }
            }
        }

        // exp (1/8 scale), row sums, fp16 P pack (hi only), PV
#pragma unroll
        for (int kc = 0; kc < 4; kc++) {
            uint32_t pah[4];
#pragma unroll
            for (int half = 0; half < 2; half++) {
                float* cc = sacc[2 * kc + half];
                float p0 = __expf(cc[0] * 0.125f), p1 = __expf(cc[1] * 0.125f);
                float p2 = __expf(cc[2] * 0.125f), p3 = __expf(cc[3] * 0.125f);
                sum0 += p0 + p1; sum1 += p2 + p3;
                pah[half * 2 + 0] = pack_f2h2(p0, p1);
                pah[half * 2 + 1] = pack_f2h2(p2, p3);
            }
#pragma unroll
            for (int ng = 0; ng < 4; ng++) {
                int row = ng * 16 + rKV;
                int c16 = 2 * kc + chKV;
                uint32_t a = st + 8192 + (uint32_t)(row * 128 + ((c16 ^ (row & 7)) << 4));
                uint32_t vh[4], vl[4];
                ldsm4(a, vh[0], vh[1], vh[2], vh[3]);
                ldsm4(a + 8192, vl[0], vl[1], vl[2], vl[3]);
#pragma unroll
                for (int hf = 0; hf < 2; hf++) {
                    float* d = oacc[ng * 2 + hf];
                    mma_f16(d, pah, &vh[hf * 2]);
                    mma_f16(d, pah, &vl[hf * 2]);
                }
            }
        }
    }
#undef LOAD_KV

    sum0 += __shfl_xor_sync(0xffffffffu, sum0, 1);
    sum0 += __shfl_xor_sync(0xffffffffu, sum0, 2);
    sum1 += __shfl_xor_sync(0xffffffffu, sum1, 1);
    sum1 += __shfl_xor_sync(0xffffffffu, sum1, 2);
    const float inv0 = 1.0f / sum0, inv1 = 1.0f / sum1;

    const int g = lane >> 2, tg = lane & 3;
    const size_t base0 = (size_t)(b * SS + q0 + wid * 16 + g) * DD + h * DHH;
#pragma unroll
    for (int nt = 0; nt < 8; nt++) {
        int col = nt * 8 + 2 * tg;
        float v0 = oacc[nt][0] * inv0, v1 = oacc[nt][1] * inv0;
        float v2 = oacc[nt][2] * inv1, v3 = oacc[nt][3] * inv1;
        __half h0, l0, h1, l1, h2, l2, h3, l3;
        hf_split(v0, h0, l0); hf_split(v1, h1, l1);
        hf_split(v2, h2, l2); hf_split(v3, h3, l3);
        *reinterpret_cast<uint32_t*>(&AOh[base0 + col]) = pack_h2(h0, h1);
        *reinterpret_cast<uint32_t*>(&AOl[base0 + col]) = pack_h2(l0, l1);
        *reinterpret_cast<uint32_t*>(&AOh[base0 + (size_t)8 * DD + col]) = pack_h2(h2, h3);
        *reinterpret_cast<uint32_t*>(&AOl[base0 + (size_t)8 * DD + col]) = pack_h2(l2, l3);
    }
}

// ===========================================================================
extern "C" void kernel_launch(void* const* d_in, const int* in_sizes, int n_in,
                              void* d_out, int out_size)
{
    const float* x  = (const float*)d_in[0];
    const float* Wq = (const float*)d_in[1];
    const float* bq = (const float*)d_in[2];
    const float* Wk = (const float*)d_in[3];
    const float* bk = (const float*)d_in[4];
    const float* Wv = (const float*)d_in[5];
    const float* bv = (const float*)d_in[6];
    const float* Wo = (const float*)d_in[7];
    const float* bo = (const float*)d_in[8];
    float* out = (float*)d_out;

    __half *xh, *xl, *Wth, *Qh, *Ql, *Kh, *Vth, *Vtl, *AOh, *AOl;
    cudaGetSymbolAddress((void**)&xh,  g_xh);  cudaGetSymbolAddress((void**)&xl,  g_xl);
    cudaGetSymbolAddress((void**)&Wth, g_Wth);
    cudaGetSymbolAddress((void**)&Qh,  g_Qh);  cudaGetSymbolAddress((void**)&Ql,  g_Ql);
    cudaGetSymbolAddress((void**)&Kh,  g_Kh);
    cudaGetSymbolAddress((void**)&Vth, g_Vth); cudaGetSymbolAddress((void**)&Vtl, g_Vtl);
    cudaGetSymbolAddress((void**)&AOh, g_AOh); cudaGetSymbolAddress((void**)&AOl, g_AOl);

    cudaFuncSetAttribute(gemm_f16x2, cudaFuncAttributeMaxDynamicSharedMemorySize, GEMM_SMEM);
    cudaFuncSetAttribute(attn_tc, cudaFuncAttributeMaxDynamicSharedMemorySize, ATTN_SMEM);

    // conversions
    conv_split<<<(MM * DD / 4 + 255) / 256, 256>>>(x, xh, xl, MM * DD / 4);
    conv_wt<<<dim3(32, 32, 4), 256>>>(Wq, Wk, Wv, Wo, Wth);

    // QKV projections (Q: fp16 hi/lo; K: fp16 hi; V: transposed fp16 hi/lo)
    gemm_f16x2<<<dim3(24, 32), 256, GEMM_SMEM>>>(
        xh, xl, Wth, bq, bk, bv,
        Qh, Ql, Kh, Vth, Vtl, (float*)nullptr, 3);

    // attention (fp16 2-term)
    attn_tc<<<dim3(SS / 128, BB * HH), 256, ATTN_SMEM>>>(
        Qh, Ql, Kh, Vth, Vtl, AOh, AOl);

    // output projection (fp32 out): A = AO (fp16 hi/lo), B = Wo slice.
    gemm_f16x2<<<dim3(8, 32), 256, GEMM_SMEM>>>(
        AOh, AOl, Wth + (size_t)3 * DD * DD, bo, bo, bo,
        (__half*)nullptr, (__half*)nullptr, (__half*)nullptr,
        (__half*)nullptr, (__half*)nullptr, out, 1);
}

// round 17
// speedup vs baseline: 1.5615x; 1.5615x over previous
#include <cuda_runtime.h>
#include <cuda_bf16.h>
#include <cuda_fp16.h>
#include <cstdint>
#include <math.h>

#define BB 2
#define SS 2048
#define DD 1024
#define HH 16
#define DHH 64
#define MM (BB * SS)

// Q is stored pre-scaled by 1/sqrt(DH) * log2(e) so attention can use exp2.
#define QSCALE 0.1803368801111204f

// ---------------- scratch (device globals: allocation-free rule) -----------
__device__ __half g_xh[(size_t)MM * DD], g_xl[(size_t)MM * DD];
__device__ __half g_Wth[(size_t)4 * DD * DD];                      // hi only
__device__ __half g_Qh[(size_t)MM * DD], g_Ql[(size_t)MM * DD];
__device__ __half g_Kh[(size_t)MM * DD];
__device__ __half g_Vth[(size_t)MM * DD], g_Vtl[(size_t)MM * DD];  // [B][D][S]
__device__ __half g_AOh[(size_t)MM * DD], g_AOl[(size_t)MM * DD];

// ---------------- helpers --------------------------------------------------
__device__ __forceinline__ uint32_t smem_to_u32(const void* p) {
    uint32_t a;
    asm("{ .reg .u64 t; cvta.to.shared.u64 t, %1; cvt.u32.u64 %0, t; }"
        : "=r"(a) : "l"(p));
    return a;
}
__device__ __forceinline__ void ldsm4(uint32_t addr, uint32_t& r0, uint32_t& r1,
                                      uint32_t& r2, uint32_t& r3) {
    asm volatile("ldmatrix.sync.aligned.m8n8.x4.shared.b16 {%0,%1,%2,%3}, [%4];"
                 : "=r"(r0), "=r"(r1), "=r"(r2), "=r"(r3) : "r"(addr));
}
__device__ __forceinline__ void mma_f16(float* d, const uint32_t* a, const uint32_t* b) {
    asm volatile(
        "mma.sync.aligned.m16n8k16.row.col.f32.f16.f16.f32 "
        "{%0,%1,%2,%3}, {%4,%5,%6,%7}, {%8,%9}, {%0,%1,%2,%3};"
        : "+f"(d[0]), "+f"(d[1]), "+f"(d[2]), "+f"(d[3])
        : "r"(a[0]), "r"(a[1]), "r"(a[2]), "r"(a[3]), "r"(b[0]), "r"(b[1]));
}
__device__ __forceinline__ void hf_split(float x, __half& h, __half& l) {
    h = __float2half_rn(x);
    l = __float2half_rn(x - __half2float(h));
}
__device__ __forceinline__ uint32_t pack_h2(__half a, __half b) {
    __half2 t(a, b);
    return *reinterpret_cast<uint32_t*>(&t);
}
__device__ __forceinline__ uint32_t pack_f2h2(float a, float b) {
    __half2 t = __floats2half2_rn(a, b);
    return *reinterpret_cast<uint32_t*>(&t);
}
#define CPA16(dst, src) \
    asm volatile("cp.async.cg.shared.global [%0], [%1], 16;" :: "r"(dst), "l"(src))
#define CPCOMMIT() asm volatile("cp.async.commit_group;" ::: "memory")
#define CPWAIT(n)  asm volatile("cp.async.wait_group %0;" :: "n"(n) : "memory")

// swizzle for [rows][32 x 16-bit] tiles (64B rows, 4x16B chunks)
__device__ __forceinline__ uint32_t swz(int row, int chunk) {
    return (uint32_t)(row * 64 + ((chunk ^ ((row >> 1) & 3)) << 4));
}
// swizzle for [rows][64 x 16-bit] tiles (128B rows, 8x16B chunks)
__device__ __forceinline__ uint32_t sw8(int row, int c8) {
    return (uint32_t)(row * 128 + ((c8 ^ (row & 7)) << 4));
}

// ---------------- conversion kernels ---------------------------------------
__global__ __launch_bounds__(256) void conv_split(
    const float* __restrict__ X, __half* __restrict__ H,
    __half* __restrict__ L, int n4)
{
    int i = blockIdx.x * 256 + threadIdx.x;
    if (i >= n4) return;
    float4 v = reinterpret_cast<const float4*>(X)[i];
    __half h0, l0, h1, l1, h2, l2, h3, l3;
    hf_split(v.x, h0, l0); hf_split(v.y, h1, l1);
    hf_split(v.z, h2, l2); hf_split(v.w, h3, l3);
    reinterpret_cast<uint2*>(H)[i] = make_uint2(pack_h2(h0, h1), pack_h2(h2, h3));
    reinterpret_cast<uint2*>(L)[i] = make_uint2(pack_h2(l0, l1), pack_h2(l2, l3));
}

__global__ __launch_bounds__(256) void conv_wt(
    const float* __restrict__ W0, const float* __restrict__ W1,
    const float* __restrict__ W2, const float* __restrict__ W3,
    __half* __restrict__ H)
{
    __shared__ float t[32][33];
    const int mat = blockIdx.z;
    const float* W = (mat == 0) ? W0 : (mat == 1) ? W1 : (mat == 2) ? W2 : W3;
    const int r0 = blockIdx.y * 32, c0 = blockIdx.x * 32;
    const int tx = threadIdx.x & 31, ty = threadIdx.x >> 5;
#pragma unroll
    for (int j = 0; j < 4; j++)
        t[ty + j * 8][tx] = W[(size_t)(r0 + ty + j * 8) * DD + c0 + tx];
    __syncthreads();
#pragma unroll
    for (int j = 0; j < 4; j++) {
        size_t dst = (size_t)mat * DD * DD + (size_t)(c0 + ty + j * 8) * DD + r0 + tx;
        H[dst] = __float2half_rn(t[tx][ty + j * 8]);
    }
}

// ===========================================================================
// fp16x2 GEMM: C = (A_h + A_l) @ W_h + bias. Pre-converted inputs,
// cp.async 3-stage ring, single barrier/chunk, 2 CTAs/SM.
// CTA tile 128x128, BK=32, 8 warps (4Mx2N).
// Stage: A_hi 8K | A_lo 8K | B_hi 8K = 24KB.
// Outputs: m=0 -> Q (fp16 hi/lo, PRE-SCALED by QSCALE), m=1 -> K (fp16 hi),
//          m=2 -> Vt (fp16 hi/lo), nmats==1 -> fp32 Cf.
// ===========================================================================
#define STG2 24576
#define GEMM_SMEM (3 * STG2)
#define NCHUNK 32

__global__ __launch_bounds__(256, 2) void gemm_f16x2(
    const __half* __restrict__ Ah, const __half* __restrict__ Al,
    const __half* __restrict__ Bth,
    const float* __restrict__ bias0, const float* __restrict__ bias1,
    const float* __restrict__ bias2,
    __half* __restrict__ Qh, __half* __restrict__ Ql,
    __half* __restrict__ Kh,
    __half* __restrict__ Vth, __half* __restrict__ Vtl,
    float* __restrict__ Cf, int nmats)
{
    extern __shared__ char smem[];
    const uint32_t sbase = smem_to_u32(smem);
    const int tid = threadIdx.x;
    const int wid = tid >> 5;
    const int lane = tid & 31;

    const int m = (nmats == 3) ? (int)(blockIdx.x >> 3) : 0;
    const __half* Bh_g = Bth + (size_t)m * DD * DD;
    const float* bias = (m == 0) ? bias0 : (m == 1) ? bias1 : bias2;
    const int bCol = (blockIdx.x & 7) * 128;
    const int bRow = blockIdx.y * 128;

    const int warpM = (wid >> 1) * 32;
    const int warpN = (wid & 1) * 64;
    const int sub = lane >> 3;
    const int li = lane & 7;

    int rA[2]; uint32_t baseA[2]; int swA[2];
#pragma unroll
    for (int fm = 0; fm < 2; fm++) {
        rA[fm] = warpM + fm * 16 + (sub & 1) * 8 + li;
        baseA[fm] = (uint32_t)(rA[fm] * 64);
        swA[fm] = (rA[fm] >> 1) & 3;
    }
    const int chA_off = sub >> 1;
    int rB[4]; uint32_t baseB[4]; int swB[4];
#pragma unroll
    for (int nb = 0; nb < 4; nb++) {
        rB[nb] = warpN + nb * 16 + ((sub >> 1) & 1) * 8 + li;
        baseB[nb] = (uint32_t)(rB[nb] * 64);
        swB[nb] = (rB[nb] >> 1) & 3;
    }
    const int chB_off = sub & 1;

    float acc[2][8][4];
#pragma unroll
    for (int fm = 0; fm < 2; fm++)
#pragma unroll
        for (int fn = 0; fn < 8; fn++)
#pragma unroll
            for (int r = 0; r < 4; r++) acc[fm][fn][r] = 0.0f;

#define LOAD_STAGE(s, c) do { \
        uint32_t st_ = sbase + (uint32_t)(s) * STG2; \
        _Pragma("unroll") \
        for (int p = 0; p < 2; p++) { \
            int id = tid + p * 256; \
            int row = id >> 2, c4 = id & 3; \
            size_t ga = (size_t)(bRow + row) * DD + (c) * 32 + c4 * 8; \
            uint32_t da = st_ + swz(row, c4); \
            CPA16(da, Ah + ga); \
            CPA16(da + 8192, Al + ga); \
            size_t gb = (size_t)(bCol + row) * DD + (c) * 32 + c4 * 8; \
            CPA16(st_ + 16384 + swz(row, c4), Bh_g + gb); \
        } \
    } while (0)

    LOAD_STAGE(0, 0); CPCOMMIT();
    LOAD_STAGE(1, 1); CPCOMMIT();

    for (int c = 0; c < NCHUNK; c++) {
        if (c < NCHUNK - 1) { CPWAIT(1); } else { CPWAIT(0); }
        __syncthreads();
        // Barrier above proves all warps done reading stage (c+2)%3.
        if (c + 2 < NCHUNK) { LOAD_STAGE((c + 2) % 3, c + 2); CPCOMMIT(); }

        const uint32_t st = sbase + (uint32_t)(c % 3) * STG2;
#pragma unroll
        for (int ks = 0; ks < 2; ks++) {
            uint32_t ah[2][4], al[2][4];
#pragma unroll
            for (int fm = 0; fm < 2; fm++) {
                uint32_t chunk = (uint32_t)((2 * ks + chA_off) ^ swA[fm]) << 4;
                ldsm4(st + baseA[fm] + chunk, ah[fm][0], ah[fm][1], ah[fm][2], ah[fm][3]);
                ldsm4(st + 8192 + baseA[fm] + chunk, al[fm][0], al[fm][1], al[fm][2], al[fm][3]);
            }
#pragma unroll
            for (int nb = 0; nb < 4; nb++) {
                uint32_t bh[4];
                uint32_t chunk = (uint32_t)((2 * ks + chB_off) ^ swB[nb]) << 4;
                ldsm4(st + 16384 + baseB[nb] + chunk, bh[0], bh[1], bh[2], bh[3]);
#pragma unroll
                for (int fm = 0; fm < 2; fm++)
#pragma unroll
                    for (int hf = 0; hf < 2; hf++) {
                        float* d = acc[fm][nb * 2 + hf];
                        mma_f16(d, ah[fm], &bh[hf * 2]);
                        mma_f16(d, al[fm], &bh[hf * 2]);
                    }
            }
        }
    }
#undef LOAD_STAGE

    // epilogue
#pragma unroll
    for (int fm = 0; fm < 2; fm++) {
        int row0 = bRow + warpM + fm * 16 + (lane >> 2);
#pragma unroll
        for (int fn = 0; fn < 8; fn++) {
            int col = bCol + warpN + fn * 8 + 2 * (lane & 3);
            float bx = bias[col], by = bias[col + 1];
            float v[4] = {acc[fm][fn][0] + bx, acc[fm][fn][1] + by,
                          acc[fm][fn][2] + bx, acc[fm][fn][3] + by};
            if (nmats == 1) {
                *reinterpret_cast<float2*>(&Cf[(size_t)row0 * DD + col]) =
                    make_float2(v[0], v[1]);
                *reinterpret_cast<float2*>(&Cf[(size_t)(row0 + 8) * DD + col]) =
                    make_float2(v[2], v[3]);
            } else if (m == 0) {
                // Q: pre-scale by 1/sqrt(DH)*log2(e) so attention uses exp2
                __half h[4], l[4];
#pragma unroll
                for (int j = 0; j < 4; j++) hf_split(v[j] * QSCALE, h[j], l[j]);
                *reinterpret_cast<uint32_t*>(&Qh[(size_t)row0 * DD + col]) = pack_h2(h[0], h[1]);
                *reinterpret_cast<uint32_t*>(&Ql[(size_t)row0 * DD + col]) = pack_h2(l[0], l[1]);
                *reinterpret_cast<uint32_t*>(&Qh[(size_t)(row0 + 8) * DD + col]) = pack_h2(h[2], h[3]);
                *reinterpret_cast<uint32_t*>(&Ql[(size_t)(row0 + 8) * DD + col]) = pack_h2(l[2], l[3]);
            } else if (m == 1) {
                *reinterpret_cast<uint32_t*>(&Kh[(size_t)row0 * DD + col]) = pack_f2h2(v[0], v[1]);
                *reinterpret_cast<uint32_t*>(&Kh[(size_t)(row0 + 8) * DD + col]) = pack_f2h2(v[2], v[3]);
            } else {
                // transposed: Vt[b][d][s], fp16 hi/lo
#pragma unroll
                for (int j = 0; j < 4; j++) {
                    int r = row0 + (j >> 1) * 8;
                    int cc = col + (j & 1);
                    size_t idx = ((size_t)(r >> 11) * DD + cc) * SS + (r & (SS - 1));
                    __half h, l; hf_split(v[j], h, l);
                    Vth[idx] = h; Vtl[idx] = l;
                }
            }
        }
    }
}

// ===========================================================================
// Tensor-core flash attention, fp16 2-term. CTA = 128 q rows of one (b,h).
// S2 = (q_h + q_l) . k_h  (Q pre-scaled; p = exp2(S2));  O += p_h.(v_h + v_l).
// Stage: Kh 8KB | Vh 8KB | Vl 8KB = 24KB; 3 stages + 32KB Q = 104KB smem.
// ===========================================================================
#define AT_STG 24576
#define AT_Q   (3 * AT_STG)
#define ATTN_SMEM (3 * AT_STG + 32768)
#define NKT 32

__global__ __launch_bounds__(256, 2) void attn_tc(
    const __half* __restrict__ Qh_g, const __half* __restrict__ Ql_g,
    const __half* __restrict__ Kh_g,
    const __half* __restrict__ Vth_g, const __half* __restrict__ Vtl_g,
    __half* __restrict__ AOh, __half* __restrict__ AOl)
{
    extern __shared__ char smem[];
    const uint32_t sb = smem_to_u32(smem);
    const int tid = threadIdx.x;
    const int wid = tid >> 5;
    const int lane = tid & 31;
    const int sub = lane >> 3;
    const int li = lane & 7;
    const int bh = blockIdx.y;
    const int b = bh >> 4, h = bh & 15;
    const int q0 = blockIdx.x * 128;

    // Q tile (hi at +0, lo at +16384)
    const uint32_t qreg = sb + AT_Q;
#pragma unroll
    for (int p = 0; p < 4; p++) {
        int id = tid + p * 256;            // 0..1023
        int row = id >> 3, c8 = id & 7;
        size_t src = (size_t)(b * SS + q0 + row) * DD + h * DHH + c8 * 8;
        CPA16(qreg + sw8(row, c8), Qh_g + src);
        CPA16(qreg + 16384 + sw8(row, c8), Ql_g + src);
    }
    CPCOMMIT();

#define LOAD_KV(s, kt) do { \
        uint32_t st_ = sb + (uint32_t)(s) * AT_STG; \
        _Pragma("unroll") \
        for (int p = 0; p < 2; p++) { \
            int id = tid + p * 256; \
            int row = id >> 3, c8 = id & 7; \
            size_t ks_ = (size_t)(b * SS + (kt) * 64 + row) * DD + h * DHH + c8 * 8; \
            CPA16(st_ + sw8(row, c8), Kh_g + ks_); \
            size_t vs_ = (size_t)(b * DD + h * DHH + row) * SS + (kt) * 64 + c8 * 8; \
            CPA16(st_ + 8192 + sw8(row, c8), Vth_g + vs_); \
            CPA16(st_ + 16384 + sw8(row, c8), Vtl_g + vs_); \
        } \
    } while (0)

    LOAD_KV(0, 0); CPCOMMIT();
    LOAD_KV(1, 1); CPCOMMIT();

    CPWAIT(2);          // Q arrived
    __syncthreads();

    // Q fragments for all 4 k-chunks (d=64), hi+lo -> registers
    uint32_t qh[4][4], ql[4][4];
    {
        int r = wid * 16 + (sub & 1) * 8 + li;
#pragma unroll
        for (int kc = 0; kc < 4; kc++) {
            int c16 = 2 * kc + (sub >> 1);
            uint32_t a = qreg + (uint32_t)(r * 128 + ((c16 ^ (r & 7)) << 4));
            ldsm4(a, qh[kc][0], qh[kc][1], qh[kc][2], qh[kc][3]);
            ldsm4(a + 16384, ql[kc][0], ql[kc][1], ql[kc][2], ql[kc][3]);
        }
    }

    float oacc[8][4];
#pragma unroll
    for (int i = 0; i < 8; i++)
#pragma unroll
        for (int j = 0; j < 4; j++) oacc[i][j] = 0.0f;
    float sum0 = 0.0f, sum1 = 0.0f;

    const int rKV = ((sub >> 1) & 1) * 8 + li;
    const int chKV = sub & 1;

    for (int kt = 0; kt < NKT; kt++) {
        if (kt < NKT - 1) { CPWAIT(1); } else { CPWAIT(0); }
        __syncthreads();
        if (kt + 2 < NKT) { LOAD_KV((kt + 2) % 3, kt + 2); CPCOMMIT(); }

        const uint32_t st = sb + (uint32_t)(kt % 3) * AT_STG;

        float sacc[8][4];
#pragma unroll
        for (int i = 0; i < 8; i++)
#pragma unroll
            for (int j = 0; j < 4; j++) sacc[i][j] = 0.0f;

#pragma unroll
        for (int kg = 0; kg < 4; kg++) {
            int row = kg * 16 + rKV;
#pragma unroll
            for (int kc = 0; kc < 4; kc++) {
                int c16 = 2 * kc + chKV;
                uint32_t a = st + (uint32_t)(row * 128 + ((c16 ^ (row & 7)) << 4));
                uint32_t kh[4];
                ldsm4(a, kh[0], kh[1], kh[2], kh[3]);
#pragma unroll
                for (int hf = 0; hf < 2; hf++) {
                    float* d = sacc[kg * 2 + hf];
                    mma_f16(d, qh[kc], &kh[hf * 2]);
                    mma_f16(d, ql[kc], &kh[hf * 2]);
                }
            }
        }

        // p = exp2(s2) (Q pre-scaled), row sums, fp16 P pack, PV
#pragma unroll
        for (int kc = 0; kc < 4; kc++) {
            uint32_t pah[4];
#pragma unroll
            for (int half = 0; half < 2; half++) {
                float* cc = sacc[2 * kc + half];
                float p0 = exp2f(cc[0]), p1 = exp2f(cc[1]);
                float p2 = exp2f(cc[2]), p3 = exp2f(cc[3]);
                sum0 += p0 + p1; sum1 += p2 + p3;
                pah[half * 2 + 0] = pack_f2h2(p0, p1);
                pah[half * 2 + 1] = pack_f2h2(p2, p3);
            }
#pragma unroll
            for (int ng = 0; ng < 4; ng++) {
                int row = ng * 16 + rKV;
                int c16 = 2 * kc + chKV;
                uint32_t a = st + 8192 + (uint32_t)(row * 128 + ((c16 ^ (row & 7)) << 4));
                uint32_t vh[4], vl[4];
                ldsm4(a, vh[0], vh[1], vh[2], vh[3]);
                ldsm4(a + 8192, vl[0], vl[1], vl[2], vl[3]);
#pragma unroll
                for (int hf = 0; hf < 2; hf++) {
                    float* d = oacc[ng * 2 + hf];
                    mma_f16(d, pah, &vh[hf * 2]);
                    mma_f16(d, pah, &vl[hf * 2]);
                }
            }
        }
    }
#undef LOAD_KV

    sum0 += __shfl_xor_sync(0xffffffffu, sum0, 1);
    sum0 += __shfl_xor_sync(0xffffffffu, sum0, 2);
    sum1 += __shfl_xor_sync(0xffffffffu, sum1, 1);
    sum1 += __shfl_xor_sync(0xffffffffu, sum1, 2);
    const float inv0 = 1.0f / sum0, inv1 = 1.0f / sum1;

    const int g = lane >> 2, tg = lane & 3;
    const size_t base0 = (size_t)(b * SS + q0 + wid * 16 + g) * DD + h * DHH;
#pragma unroll
    for (int nt = 0; nt < 8; nt++) {
        int col = nt * 8 + 2 * tg;
        float v0 = oacc[nt][0] * inv0, v1 = oacc[nt][1] * inv0;
        float v2 = oacc[nt][2] * inv1, v3 = oacc[nt][3] * inv1;
        __half h0, l0, h1, l1, h2, l2, h3, l3;
        hf_split(v0, h0, l0); hf_split(v1, h1, l1);
        hf_split(v2, h2, l2); hf_split(v3, h3, l3);
        *reinterpret_cast<uint32_t*>(&AOh[base0 + col]) = pack_h2(h0, h1);
        *reinterpret_cast<uint32_t*>(&AOl[base0 + col]) = pack_h2(l0, l1);
        *reinterpret_cast<uint32_t*>(&AOh[base0 + (size_t)8 * DD + col]) = pack_h2(h2, h3);
        *reinterpret_cast<uint32_t*>(&AOl[base0 + (size_t)8 * DD + col]) = pack_h2(l2, l3);
    }
}

// ===========================================================================
extern "C" void kernel_launch(void* const* d_in, const int* in_sizes, int n_in,
                              void* d_out, int out_size)
{
    const float* x  = (const float*)d_in[0];
    const float* Wq = (const float*)d_in[1];
    const float* bq = (const float*)d_in[2];
    const float* Wk = (const float*)d_in[3];
    const float* bk = (const float*)d_in[4];
    const float* Wv = (const float*)d_in[5];
    const float* bv = (const float*)d_in[6];
    const float* Wo = (const float*)d_in[7];
    const float* bo = (const float*)d_in[8];
    float* out = (float*)d_out;

    __half *xh, *xl, *Wth, *Qh, *Ql, *Kh, *Vth, *Vtl, *AOh, *AOl;
    cudaGetSymbolAddress((void**)&xh,  g_xh);  cudaGetSymbolAddress((void**)&xl,  g_xl);
    cudaGetSymbolAddress((void**)&Wth, g_Wth);
    cudaGetSymbolAddress((void**)&Qh,  g_Qh);  cudaGetSymbolAddress((void**)&Ql,  g_Ql);
    cudaGetSymbolAddress((void**)&Kh,  g_Kh);
    cudaGetSymbolAddress((void**)&Vth, g_Vth); cudaGetSymbolAddress((void**)&Vtl, g_Vtl);
    cudaGetSymbolAddress((void**)&AOh, g_AOh); cudaGetSymbolAddress((void**)&AOl, g_AOl);

    cudaFuncSetAttribute(gemm_f16x2, cudaFuncAttributeMaxDynamicSharedMemorySize, GEMM_SMEM);
    cudaFuncSetAttribute(attn_tc, cudaFuncAttributeMaxDynamicSharedMemorySize, ATTN_SMEM);

    // conversions
    conv_split<<<(MM * DD / 4 + 255) / 256, 256>>>(x, xh, xl, MM * DD / 4);
    conv_wt<<<dim3(32, 32, 4), 256>>>(Wq, Wk, Wv, Wo, Wth);

    // QKV projections (Q: fp16 hi/lo pre-scaled; K: fp16 hi; V: transposed)
    gemm_f16x2<<<dim3(24, 32), 256, GEMM_SMEM>>>(
        xh, xl, Wth, bq, bk, bv,
        Qh, Ql, Kh, Vth, Vtl, (float*)nullptr, 3);

    // attention (fp16 2-term, exp2)
    attn_tc<<<dim3(SS / 128, BB * HH), 256, ATTN_SMEM>>>(
        Qh, Ql, Kh, Vth, Vtl, AOh, AOl);

    // output projection (fp32 out): A = AO (fp16 hi/lo), B = Wo slice.
    gemm_f16x2<<<dim3(8, 32), 256, GEMM_SMEM>>>(
        AOh, AOl, Wth + (size_t)3 * DD * DD, bo, bo, bo,
        (__half*)nullptr, (__half*)nullptr, (__half*)nullptr,
        (__half*)nullptr, (__half*)nullptr, out, 1);
}